// round 17
// baseline (speedup 1.0000x reference)
#include <cuda_runtime.h>
#include <cstdint>

#define VOCAB 32000
#define EMB   256
#define HID   512
#define NOUT  5
#define SEQ   512
#define BATCH 64
#define G3    1536   // 3*HID

// ---------------- scratch (static device allocations only) ----------------
__device__ float g_xg[(size_t)SEQ * BATCH * G3];   // 201 MB: precomputed input gates
__device__ float g_h[2][BATCH * HID];              // double-buffered hidden state
__device__ float g_hfinal[BATCH * HID];            // final hidden per batch

struct alignas(128) PadInt { int v; int pad[31]; };
__device__ PadInt g_flag[8][16];   // per-(group,CTA) step flag, own 128-B line

// ---------------- packed fp32x2 FMA (Blackwell; 2x FFMA throughput) -------
__device__ __forceinline__ void ffma2(unsigned long long& acc,
                                      unsigned long long a,
                                      unsigned long long b) {
    asm("fma.rn.f32x2 %0, %1, %2, %0;" : "+l"(acc) : "l"(a), "l"(b));
}
__device__ __forceinline__ float hsum2(unsigned long long v) {
    float lo = __uint_as_float((unsigned)(v & 0xffffffffull));
    float hi = __uint_as_float((unsigned)(v >> 32));
    return lo + hi;
}
__device__ __forceinline__ int ld_acq(const int* p) {
    int v; asm volatile("ld.global.acquire.gpu.b32 %0, [%1];" : "=r"(v) : "l"(p)); return v;
}
__device__ __forceinline__ void st_rel(int* p, int v) {
    asm volatile("st.global.release.gpu.b32 [%0], %1;" :: "l"(p), "r"(v));
}
__device__ __forceinline__ void cp16(uint32_t sdst, const void* gsrc) {
    asm volatile("cp.async.cg.shared.global [%0], [%1], 16;"
                 :: "r"(sdst), "l"(gsrc) : "memory");
}

// ---------------- phase 1: x_gates = emb[seq] @ w_ih^T + b_ih -------------
#define P1_SMEM ((64 * 260 + 128 * 258) * 4)
__global__ void __launch_bounds__(256, 1)
k_xgates(const int* __restrict__ seq, const int* __restrict__ lengths,
         const float* __restrict__ emb, const float* __restrict__ w_ih,
         const float* __restrict__ b_ih) {
    const int b = blockIdx.x, st = blockIdx.y, nc = blockIdx.z;
    const int s0 = st * 64, n0 = nc * 128;
    const int tid = threadIdx.x;

    if (b == 0 && st == 0 && nc == 0 && tid < 128)
        g_flag[tid >> 4][tid & 15].v = 0;
    if (s0 >= lengths[b]) return;  // dead steps never read downstream

    extern __shared__ float sm1[];
    float* xs = sm1;               // [64][260]
    float* ws = sm1 + 64 * 260;    // [128][258] = [kp][129 float2]

    {
        int r = tid >> 2, part = tid & 3;
        int tok = seq[(s0 + r) * BATCH + b];
        const float4* src = reinterpret_cast<const float4*>(emb) +
                            (size_t)tok * (EMB / 4) + part * 16;
        float* drow = xs + r * 260;
#pragma unroll
        for (int i = 0; i < 16; ++i) {
            float4 v = src[i];
            int k = (part * 16 + i) * 4;
            drow[k] = v.x; drow[k + 1] = v.y; drow[k + 2] = v.z; drow[k + 3] = v.w;
        }
    }
    {
        int n = tid >> 1, half = tid & 1;
        const float4* src = reinterpret_cast<const float4*>(
            w_ih + (size_t)(n0 + n) * EMB + half * 128);
#pragma unroll
        for (int i = 0; i < 32; ++i) {
            float4 v = src[i];
            int kp = half * 64 + i * 2;
            float* d0 = ws + (kp * 129 + n) * 2;
            d0[0] = v.x; d0[1] = v.y;
            float* d1 = ws + ((kp + 1) * 129 + n) * 2;
            d1[0] = v.z; d1[1] = v.w;
        }
    }
    __syncthreads();

    const int tn = tid & 15, ts = tid >> 4;
    unsigned long long acc[4][8];
#pragma unroll
    for (int i = 0; i < 4; ++i)
#pragma unroll
        for (int j = 0; j < 8; ++j) acc[i][j] = 0ull;

    const float* xbase = xs + ts * 260;
#pragma unroll 2
    for (int kp = 0; kp < 128; ++kp) {
        unsigned long long a[4], w[8];
#pragma unroll
        for (int i = 0; i < 4; ++i)
            a[i] = *reinterpret_cast<const unsigned long long*>(xbase + i * 16 * 260 + 2 * kp);
#pragma unroll
        for (int j = 0; j < 8; ++j)
            w[j] = *reinterpret_cast<const unsigned long long*>(ws + (kp * 129 + j * 16 + tn) * 2);
#pragma unroll
        for (int i = 0; i < 4; ++i)
#pragma unroll
            for (int j = 0; j < 8; ++j) ffma2(acc[i][j], a[i], w[j]);
    }
#pragma unroll
    for (int i = 0; i < 4; ++i) {
        int s = s0 + ts + i * 16;
        float* orow = g_xg + ((size_t)s * BATCH + b) * G3 + n0;
#pragma unroll
        for (int j = 0; j < 8; ++j) {
            int n = j * 16 + tn;
            orow[n] = hsum2(acc[i][j]) + b_ih[n0 + n];
        }
    }
}

// ---------------- phase 2: persistent GRU, producer-granular pipeline -----
// grid 148 (low-grid throttle avoidance); CTAs 128..147 exit. cid=16g+kg.
// K split into 16 chunks of 32 floats (one per producer CTA). Per step:
// 4-stage pipeline over super-chunks of 4 producers:
//   wait 4 flags -> cp.async 4KB -> (wait_group 1; sync) -> GEMM prev chunk
// so producer skew and L2 latency overlap the GEMM of already-arrived
// chunks. GEMM thread = (qh 0..47, kl 0..7): rows {qh, qh+48}, one float4
// per chunk, NB batches. Weights [kp2][97 pad] float4 (conflict-free);
// 8 kl-partials folded to 4 slots (hgp stride 97).
#define W4_STRIDE 97
#define HGP_S     776                      // 8 * 97 floats per kqm slot
#define P2_SMEM   ((128 * W4_STRIDE * 4 + 16 * 64 * 4 + 4 * HGP_S) * 4)

template <int NB>
__device__ __forceinline__ void gru_step_mm(
    const float4* __restrict__ w4, const float4* __restrict__ hsm4,
    float* __restrict__ hgp, const float* __restrict__ hr,
    uint32_t hsm_a, const int* __restrict__ fl, int t, int g,
    int tid, int lane, int qh, int kl)
{
    unsigned long long accA0[NB], accA1[NB], accB0[NB], accB1[NB];
#pragma unroll
    for (int b = 0; b < NB; ++b) { accA0[b] = 0; accA1[b] = 0; accB0[b] = 0; accB1[b] = 0; }

    const int st_b  = tid >> 5;        // 0..7   (stage roles, tid<256)
    const int st_pl = (tid >> 3) & 3;  // 0..3
    const int st_f4 = tid & 7;         // 0..7

    auto wait4 = [&](int s) {
        int v;
        do { v = (lane < 4) ? ld_acq(fl + (4 * s + lane) * 32) : 0x7fffffff; }
        while (__any_sync(0xffffffffu, v < t));
    };
    auto stage = [&](int s) {
        if (tid < 256) {
            int p = 4 * s + st_pl;
            cp16(hsm_a + (uint32_t)((p * 64 + st_b * 8 + st_f4) * 16),
                 hr + (size_t)(g + 8 * st_b) * HID + p * 32 + st_f4 * 4);
        }
        asm volatile("cp.async.commit_group;" ::: "memory");
    };
    auto mm = [&](int s) {
#pragma unroll
        for (int pc = 0; pc < 4; ++pc) {
            const int p = 4 * s + pc;
            const float4* wrow = w4 + (size_t)(8 * p + kl) * W4_STRIDE;
            ulonglong2 wA = *reinterpret_cast<const ulonglong2*>(wrow + qh);
            ulonglong2 wB = *reinterpret_cast<const ulonglong2*>(wrow + qh + 48);
            const ulonglong2* hc =
                reinterpret_cast<const ulonglong2*>(hsm4 + p * 64 + kl);
#pragma unroll
            for (int b = 0; b < NB; ++b) {
                ulonglong2 h = hc[b * 8];
                ffma2(accA0[b], wA.x, h.x); ffma2(accA1[b], wA.y, h.y);
                ffma2(accB0[b], wB.x, h.x); ffma2(accB1[b], wB.y, h.y);
            }
        }
    };

    wait4(0); stage(0);
    wait4(1); stage(1);
    asm volatile("cp.async.wait_group 1;" ::: "memory");
    __syncthreads();
    mm(0);
    wait4(2); stage(2);
    asm volatile("cp.async.wait_group 1;" ::: "memory");
    __syncthreads();
    mm(1);
    wait4(3); stage(3);
    asm volatile("cp.async.wait_group 1;" ::: "memory");
    __syncthreads();
    mm(2);
    asm volatile("cp.async.wait_group 0;" ::: "memory");
    __syncthreads();
    mm(3);

    // fold 8 kl-partials to 4 slots: kl<4 writes, kl>=4 adds
    float vA[NB], vB[NB];
#pragma unroll
    for (int b = 0; b < NB; ++b) {
        vA[b] = hsum2(accA0[b]) + hsum2(accA1[b]);
        vB[b] = hsum2(accB0[b]) + hsum2(accB1[b]);
    }
    float* oA = hgp + (kl & 3) * HGP_S + qh;
    float* oB = oA + 48;
    if (kl < 4) {
#pragma unroll
        for (int b = 0; b < NB; ++b) { oA[b * 97] = vA[b]; oB[b * 97] = vB[b]; }
    }
    __syncthreads();
    if (kl >= 4) {
#pragma unroll
        for (int b = 0; b < NB; ++b) { oA[b * 97] += vA[b]; oB[b * 97] += vB[b]; }
    }
    __syncthreads();
}

__global__ void __launch_bounds__(384, 1)
k_gru(const float* __restrict__ w_hh, const float* __restrict__ b_hh,
      const int* __restrict__ lengths, const float* __restrict__ w_out,
      const float* __restrict__ b_out, float* __restrict__ out) {
    const int cid = blockIdx.x;
    if (cid >= 128) return;            // pad CTAs exit immediately
    const int kg = cid & 15;           // 0..15 hidden slice
    const int g  = cid >> 4;           // 0..7  batch group
    const int j0 = kg * 32;

    extern __shared__ float sm2[];
    float4* w4   = reinterpret_cast<float4*>(sm2);       // [128][97] f4
    float4* hsm4 = w4 + 128 * W4_STRIDE;                  // [16 p][8 b][8 f4]
    float*  hgp  = reinterpret_cast<float*>(hsm4 + 16 * 64); // [4][8][97]
    __shared__ int   len_loc[8];
    __shared__ float lg[8][NOUT];

    const int tid  = threadIdx.x;
    const int lane = tid & 31;
    const int qh   = tid >> 3;          // 0..47 (rows qh, qh+48)
    const int kl   = tid & 7;           // 0..7  (float4 within chunk)
    const uint32_t hsm_a = (uint32_t)__cvta_generic_to_shared(hsm4);

    if (tid < 8) len_loc[tid] = lengths[g + 8 * tid];

    // persistent weight slice (once): w4[kp2*97+q] = w_hh[row(q)][4kp2..]
    for (int idx = tid; idx < 96 * 128; idx += 384) {
        int qq = idx >> 7, kp2 = idx & 127;
        int row = (qq / 32) * HID + j0 + (qq % 32);
        w4[kp2 * W4_STRIDE + qq] =
            *(reinterpret_cast<const float4*>(w_hh + (size_t)row * HID) + kp2);
    }
    __syncthreads();

    const int nsteps = len_loc[0];      // lengths descending in bl

    // ---- pointwise thread state (tid < 256 handles one (bl, jl)) ----
    const bool pw = (tid < 256);
    const int bl = tid >> 5, jl = tid & 31;
    const int bg = g + 8 * bl;
    int mylen = 0;
    float bhr = 0.f, bhz = 0.f, bhn = 0.f;
    const float* xp = nullptr;
    size_t hoff = 0;
    float hcur = 0.f;
    if (pw) {
        mylen = len_loc[bl];
        bhr = b_hh[j0 + jl];
        bhz = b_hh[HID + j0 + jl];
        bhn = b_hh[2 * HID + j0 + jl];
        xp  = g_xg + (size_t)bg * G3 + j0 + jl;
        hoff = (size_t)bg * HID + j0 + jl;
    }

    const int* fl = &g_flag[g][0].v;    // flag i at fl[i*32]
    int* myfl = &g_flag[g][kg].v;

    for (int t = 0; t < nsteps; ++t) {
        float* hw = g_h[(t + 1) & 1];

        // prefetch this step's xg (DRAM) -- in flight through wait + GEMM
        float x0 = 0.f, x1 = 0.f, x2 = 0.f;
        const bool act = pw && (t < mylen);
        if (act) {
            x0 = __ldcs(xp);
            x1 = __ldcs(xp + HID);
            x2 = __ldcs(xp + 2 * HID);
            xp += (size_t)BATCH * G3;
        }

        if (t > 0) {
            const float* hr = g_h[t & 1];
            int A = 0;
#pragma unroll
            for (int i = 0; i < 8; ++i) A += (t < len_loc[i]) ? 1 : 0;

            if (A > 4)
                gru_step_mm<8>(w4, hsm4, hgp, hr, hsm_a, fl, t, g, tid, lane, qh, kl);
            else
                gru_step_mm<4>(w4, hsm4, hgp, hr, hsm_a, fl, t, g, tid, lane, qh, kl);
        }

        // ---- pointwise GRU update (h element lives in hcur register) ----
        if (act) {
            float sr = 0.f, sz = 0.f, sn = 0.f;
            if (t > 0) {
                const float* hgb = hgp + bl * 97 + jl;
                sr = hgb[0]  + hgb[HGP_S]      + hgb[2 * HGP_S]      + hgb[3 * HGP_S];
                sz = hgb[32] + hgb[HGP_S + 32] + hgb[2 * HGP_S + 32] + hgb[3 * HGP_S + 32];
                sn = hgb[64] + hgb[HGP_S + 64] + hgb[2 * HGP_S + 64] + hgb[3 * HGP_S + 64];
            }
            float gr  = sr + bhr + x0;
            float gz  = sz + bhz + x1;
            float gnh = sn + bhn;
            float r = 1.0f / (1.0f + __expf(-gr));
            float z = 1.0f / (1.0f + __expf(-gz));
            float n = tanhf(x2 + r * gnh);
            hcur = (1.0f - z) * n + z * hcur;
            __stcg(hw + hoff, hcur);
        }

        // ---- publish: one release-store on our own padded line ----
        __syncthreads();                // all h stores issued CTA-wide
        if (tid == 0) st_rel(myfl, t + 1);
        // next iteration's flag waits subsume the trailing sync
    }

    // ---- final round: publish h, flag once more, kg==0 computes head ----
    if (pw) __stcg(&g_hfinal[hoff], hcur);
    __syncthreads();
    if (tid == 0) st_rel(myfl, nsteps + 1);

    if (kg == 0) {
        {
            int v;
            do {
                v = (lane < 16) ? ld_acq(fl + lane * 32) : 0x7fffffff;
            } while (__any_sync(0xffffffffu, v < nsteps + 1));
        }
        const int wid = tid >> 5;
        for (int p = wid; p < 8 * NOUT; p += 12) {
            int bb = p / NOUT, oo = p % NOUT;
            const float4* h4 =
                reinterpret_cast<const float4*>(g_hfinal + (size_t)(g + 8 * bb) * HID);
            const float4* w4o =
                reinterpret_cast<const float4*>(w_out + (size_t)oo * HID);
            float s = 0.f;
#pragma unroll
            for (int i = 0; i < 4; ++i) {
                float4 hv = __ldcg(h4 + lane + 32 * i);
                float4 wv = w4o[lane + 32 * i];
                s += hv.x * wv.x + hv.y * wv.y + hv.z * wv.z + hv.w * wv.w;
            }
#pragma unroll
            for (int d = 16; d; d >>= 1) s += __shfl_down_sync(0xffffffffu, s, d);
            if (lane == 0) lg[bb][oo] = s + b_out[oo];
        }
        __syncthreads();
        if (tid < 8) {
            float m = lg[tid][0];
#pragma unroll
            for (int i = 1; i < NOUT; ++i) m = fmaxf(m, lg[tid][i]);
            float sum = 0.f;
#pragma unroll
            for (int i = 0; i < NOUT; ++i) sum += __expf(lg[tid][i] - m);
            float lse = m + logf(sum);
#pragma unroll
            for (int i = 0; i < NOUT; ++i)
                out[(g + 8 * tid) * NOUT + i] = lg[tid][i] - lse;
        }
    }
}

// ---------------- launch ---------------------------------------------------
extern "C" void kernel_launch(void* const* d_in, const int* in_sizes, int n_in,
                              void* d_out, int out_size) {
    const int*   seq     = (const int*)d_in[0];
    const int*   lengths = (const int*)d_in[1];
    const float* emb     = (const float*)d_in[2];
    const float* w_ih    = (const float*)d_in[3];
    const float* w_hh    = (const float*)d_in[4];
    const float* b_ih    = (const float*)d_in[5];
    const float* b_hh    = (const float*)d_in[6];
    const float* w_out   = (const float*)d_in[7];
    const float* b_out   = (const float*)d_in[8];
    float*       out     = (float*)d_out;

    cudaFuncSetAttribute(k_xgates, cudaFuncAttributeMaxDynamicSharedMemorySize, P1_SMEM);
    cudaFuncSetAttribute(k_gru,    cudaFuncAttributeMaxDynamicSharedMemorySize, P2_SMEM);

    k_xgates<<<dim3(BATCH, SEQ / 64, G3 / 128), 256, P1_SMEM>>>(seq, lengths, emb, w_ih, b_ih);
    k_gru<<<148, 384, P2_SMEM>>>(w_hh, b_hh, lengths, w_out, b_out, out);
}